// round 12
// baseline (speedup 1.0000x reference)
#include <cuda_runtime.h>
#include <cuda_fp16.h>

#define MAXN   200000
#define CIN    32
#define HID    192
#define KOFF   9
#define COUT   32
#define EPSV   1e-5f
#define HHALF  96      // channels per half
#define NCHH   12      // uint4 chunks per half (12*8=96)

// fp16 scratch split into channel halves so each depthwise gather pass has a
// 38.4MB working set that stays L2-resident (126MB L2) next to the z stream.
__device__ __half g_x1a[(size_t)MAXN * HHALF];
__device__ __half g_x1b[(size_t)MAXN * HHALF];
__device__ __half g_za [(size_t)MAXN * HHALF];
__device__ __half g_zb [(size_t)MAXN * HHALF];

// prep-kernel outputs: fragment-packed weights + folded BN constants
__device__ unsigned g_W1f[24 * 2 * 2 * 32];   // [w][s][i][lane]
__device__ unsigned g_W3f[4 * 12 * 2 * 32];   // [j][s][i][lane]
__device__ float g_s1[HID], g_c1[HID];
__device__ float g_s2[HID], g_c2[HID];
__device__ float g_s3[COUT], g_c3[COUT];

__device__ __forceinline__ float relu6f(float x) {
    return fminf(fmaxf(x, 0.0f), 6.0f);
}
__device__ __forceinline__ float2 h2tof2(unsigned int u) {
    __half2 h = *reinterpret_cast<__half2*>(&u);
    return __half22float2(h);
}
__device__ __forceinline__ unsigned int f2toh2(float a, float b) {
    __half2 h = __floats2half2_rn(a, b);
    return *reinterpret_cast<unsigned int*>(&h);
}
__device__ __forceinline__ unsigned int packh(__half lo, __half hi) {
    __half2 h = __halves2half2(lo, hi);
    return *reinterpret_cast<unsigned int*>(&h);
}

// m16n8k16 fp16 x fp16 -> fp32 MMA
__device__ __forceinline__ void mma16816(
    float& d0, float& d1, float& d2, float& d3,
    unsigned a0, unsigned a1, unsigned a2, unsigned a3,
    unsigned b0, unsigned b1)
{
    asm volatile(
        "mma.sync.aligned.m16n8k16.row.col.f32.f16.f16.f32 "
        "{%0,%1,%2,%3}, {%4,%5,%6,%7}, {%8,%9}, {%0,%1,%2,%3};\n"
        : "+f"(d0), "+f"(d1), "+f"(d2), "+f"(d3)
        : "r"(a0), "r"(a1), "r"(a2), "r"(a3), "r"(b0), "r"(b1));
}

// ---------------------------------------------------------------------------
// Prep: pack W1/W3 into fragment-ready lane-major arrays, fold BN constants.
// One block, 768 threads, ~2us.
// ---------------------------------------------------------------------------
__global__ void __launch_bounds__(768) k_prep(
    const float* __restrict__ W1, const float* __restrict__ W3,
    const float* __restrict__ g1, const float* __restrict__ b1,
    const float* __restrict__ m1, const float* __restrict__ v1,
    const float* __restrict__ g2, const float* __restrict__ b2,
    const float* __restrict__ m2, const float* __restrict__ v2,
    const float* __restrict__ g3, const float* __restrict__ b3,
    const float* __restrict__ m3, const float* __restrict__ v3)
{
    const int tid  = threadIdx.x;
    const int lane = tid & 31;
    const int g    = lane >> 2;
    const int t    = lane & 3;

    // W1 fragments: 24 warp-tiles x 2 k-steps x 2 regs
    {
        const int w = tid >> 5;           // 0..23
        const int col = w * 8 + g;
#pragma unroll
        for (int s = 0; s < 2; s++)
#pragma unroll
            for (int i = 0; i < 2; i++) {
                const int k0 = 16 * s + 2 * t + 8 * i;
                g_W1f[((w * 2 + s) * 2 + i) * 32 + lane] =
                    packh(__float2half(W1[(k0)     * HID + col]),
                          __float2half(W1[(k0 + 1) * HID + col]));
            }
    }
    // W3 fragments: 4 n-tiles x 12 k-steps x 2 regs
    if (tid < 128) {
        const int j = tid >> 5;           // 0..3
        const int col = j * 8 + g;
#pragma unroll
        for (int s = 0; s < 12; s++)
#pragma unroll
            for (int i = 0; i < 2; i++) {
                const int k0 = 16 * s + 2 * t + 8 * i;
                g_W3f[((j * 12 + s) * 2 + i) * 32 + lane] =
                    packh(__float2half(W3[(k0)     * COUT + col]),
                          __float2half(W3[(k0 + 1) * COUT + col]));
            }
    }
    if (tid < HID) {
        float s = g1[tid] * rsqrtf(v1[tid] + EPSV);
        g_s1[tid] = s; g_c1[tid] = b1[tid] - m1[tid] * s;
        s = g2[tid] * rsqrtf(v2[tid] + EPSV);
        g_s2[tid] = s; g_c2[tid] = b2[tid] - m2[tid] * s;
    }
    if (tid < COUT) {
        const float s = g3[tid] * rsqrtf(v3[tid] + EPSV);
        g_s3[tid] = s; g_c3[tid] = b3[tid] - m3[tid] * s;
    }
}

// ---------------------------------------------------------------------------
// Kernel 1 (MMA): expand 1x1 conv + BN1 + relu6 -> g_x1a/g_x1b (fp16)
// Block = 768 thr = 24 warps; warp w owns output cols [8w, 8w+8).
// 64-row tile; feats staged fp16 in smem (stride 40 halves, conflict-free).
// ---------------------------------------------------------------------------
#define FST   40
#define XST   208   // epilogue smem stride (halves) = 26 uint4

__global__ void __launch_bounds__(768) k_expand(
    const float* __restrict__ feats, int N)
{
    __shared__ __align__(16) __half sf[64 * FST];
    __shared__ __align__(16) __half sx[64 * XST];

    const int tid  = threadIdx.x;
    const int w    = tid >> 5;
    const int lane = tid & 31;
    const int g    = lane >> 2;
    const int t    = lane & 3;
    const int colb = w * 8;
    const int c0   = colb + 2 * t;

    unsigned bf[2][2];
#pragma unroll
    for (int s = 0; s < 2; s++)
#pragma unroll
        for (int i = 0; i < 2; i++)
            bf[s][i] = g_W1f[((w * 2 + s) * 2 + i) * 32 + lane];

    const float2 sv = *reinterpret_cast<const float2*>(g_s1 + c0);
    const float2 cv = *reinterpret_cast<const float2*>(g_c1 + c0);

    const int r0 = blockIdx.x * 64;

#pragma unroll
    for (int i = tid; i < 64 * CIN; i += 768) {
        const int r = i >> 5, c = i & 31;
        const int row = r0 + r;
        const float v = (row < N) ? feats[row * CIN + c] : 0.0f;
        sf[r * FST + c] = __float2half(v);
    }
    __syncthreads();

#pragma unroll
    for (int sub = 0; sub < 4; sub++) {
        float d0 = 0.f, d1 = 0.f, d2 = 0.f, d3 = 0.f;
        const __half* base = sf + (sub * 16) * FST;
#pragma unroll
        for (int s = 0; s < 2; s++) {
            const int ko = 2 * t + 16 * s;
            unsigned a0 = *reinterpret_cast<const unsigned*>(base + g * FST + ko);
            unsigned a1 = *reinterpret_cast<const unsigned*>(base + (g + 8) * FST + ko);
            unsigned a2 = *reinterpret_cast<const unsigned*>(base + g * FST + ko + 8);
            unsigned a3 = *reinterpret_cast<const unsigned*>(base + (g + 8) * FST + ko + 8);
            mma16816(d0, d1, d2, d3, a0, a1, a2, a3, bf[s][0], bf[s][1]);
        }
        const int rlo = sub * 16 + g;
        const int rhi = rlo + 8;
        *reinterpret_cast<unsigned*>(sx + rlo * XST + c0) =
            f2toh2(relu6f(fmaf(d0, sv.x, cv.x)), relu6f(fmaf(d1, sv.y, cv.y)));
        *reinterpret_cast<unsigned*>(sx + rhi * XST + c0) =
            f2toh2(relu6f(fmaf(d2, sv.x, cv.x)), relu6f(fmaf(d3, sv.y, cv.y)));
    }
    __syncthreads();

    // coalesced split store: chunks 0-11 -> x1a, 12-23 -> x1b
    uint4* xa = reinterpret_cast<uint4*>(g_x1a);
    uint4* xb = reinterpret_cast<uint4*>(g_x1b);
    const uint4* sxb = reinterpret_cast<const uint4*>(sx);
#pragma unroll
    for (int i = tid; i < 64 * 24; i += 768) {
        const int r = i / 24, ch = i % 24;
        const int row = r0 + r;
        if (row < N) {
            const uint4 v = sxb[r * 26 + ch];
            if (ch < NCHH) xa[(size_t)row * NCHH + ch]          = v;
            else           xb[(size_t)row * NCHH + (ch - NCHH)] = v;
        }
    }
}

// ---------------------------------------------------------------------------
// Kernel 2: depthwise sparse conv, one channel-half per launch (templated on
// HALF so the scratch arrays are referenced directly — no symbol-address API
// in kernel_launch). Thread = (1 row, one 8-chunk). 9 gathers front-batched.
// ---------------------------------------------------------------------------
template <int HALF>
__global__ void __launch_bounds__(256) k_dw_half(
    const int* __restrict__ nbr, const float* __restrict__ W2, int N)
{
    const __half* __restrict__ xh = (HALF == 0) ? g_x1a : g_x1b;
    __half* __restrict__ zh       = (HALF == 0) ? g_za  : g_zb;
    const int co = HALF * HHALF;

    __shared__ __align__(16) float W2s[KOFF * HHALF];

    const int tid = threadIdx.x;
    for (int i = tid; i < KOFF * HHALF; i += 256)
        W2s[i] = W2[(i / HHALF) * HID + co + (i % HHALF)];
    __syncthreads();

    const int gid = blockIdx.x * 256 + tid;
    const int ch  = gid % NCHH;
    const int row = gid / NCHH;
    if (row >= N) return;
    const int ch8 = ch * 8;

    int ids[KOFF];
#pragma unroll
    for (int k = 0; k < KOFF; k++) ids[k] = nbr[row * KOFF + k];

    const uint4* xb = reinterpret_cast<const uint4*>(xh);
    uint4 v[KOFF];
#pragma unroll
    for (int k = 0; k < KOFF; k++) {
        v[k] = make_uint4(0u, 0u, 0u, 0u);
        if (ids[k] >= 0) v[k] = xb[ids[k] * NCHH + ch];
    }

    float a0 = 0.f, a1 = 0.f, a2 = 0.f, a3 = 0.f;
    float a4 = 0.f, a5 = 0.f, a6 = 0.f, a7 = 0.f;
#pragma unroll
    for (int k = 0; k < KOFF; k++) {
        const float4 wA = *reinterpret_cast<const float4*>(W2s + k * HHALF + ch8);
        const float4 wB = *reinterpret_cast<const float4*>(W2s + k * HHALF + ch8 + 4);
        const float2 f0 = h2tof2(v[k].x);
        const float2 f1 = h2tof2(v[k].y);
        const float2 f2 = h2tof2(v[k].z);
        const float2 f3 = h2tof2(v[k].w);
        a0 = fmaf(f0.x, wA.x, a0);
        a1 = fmaf(f0.y, wA.y, a1);
        a2 = fmaf(f1.x, wA.z, a2);
        a3 = fmaf(f1.y, wA.w, a3);
        a4 = fmaf(f2.x, wB.x, a4);
        a5 = fmaf(f2.y, wB.y, a5);
        a6 = fmaf(f3.x, wB.z, a6);
        a7 = fmaf(f3.y, wB.w, a7);
    }

    const float4 sA = *reinterpret_cast<const float4*>(g_s2 + co + ch8);
    const float4 sB = *reinterpret_cast<const float4*>(g_s2 + co + ch8 + 4);
    const float4 cA = *reinterpret_cast<const float4*>(g_c2 + co + ch8);
    const float4 cB = *reinterpret_cast<const float4*>(g_c2 + co + ch8 + 4);

    uint4 o;
    o.x = f2toh2(relu6f(fmaf(a0, sA.x, cA.x)), relu6f(fmaf(a1, sA.y, cA.y)));
    o.y = f2toh2(relu6f(fmaf(a2, sA.z, cA.z)), relu6f(fmaf(a3, sA.w, cA.w)));
    o.z = f2toh2(relu6f(fmaf(a4, sB.x, cB.x)), relu6f(fmaf(a5, sB.y, cB.y)));
    o.w = f2toh2(relu6f(fmaf(a6, sB.z, cB.z)), relu6f(fmaf(a7, sB.w, cB.w)));
    reinterpret_cast<uint4*>(zh)[(size_t)row * NCHH + ch] = o;
}

// ---------------------------------------------------------------------------
// Kernel 3 (MMA): project 1x1 conv (z @ W3) + BN3 + residual -> out (fp32)
// Block = 512 thr = 16 warps; warp w: n-tile j=w&3, row-subtile rs=w>>2.
// z staged from the two halves into one fp16 tile (stride 200 halves,
// conflict-free). B-fragments loaded coalesced from prep-packed g_W3f.
// ---------------------------------------------------------------------------
#define ZST 200   // halves; 25 uint4 per row

__global__ void __launch_bounds__(512) k_proj(
    const float* __restrict__ feats, float* __restrict__ out, int N)
{
    __shared__ __align__(16) __half zs[64 * ZST];

    const int tid  = threadIdx.x;
    const int w    = tid >> 5;
    const int lane = tid & 31;
    const int g    = lane >> 2;
    const int t    = lane & 3;
    const int j    = w & 3;
    const int rs   = w >> 2;
    const int colb = 8 * j;
    const int c0   = colb + 2 * t;

    const int r0 = blockIdx.x * 64;

    // stage z tile from both halves: 64 rows x 24 uint4 (coalesced)
    const uint4* za = reinterpret_cast<const uint4*>(g_za);
    const uint4* zb = reinterpret_cast<const uint4*>(g_zb);
    uint4* zsb = reinterpret_cast<uint4*>(zs);
#pragma unroll
    for (int i = tid; i < 64 * 24; i += 512) {
        const int r = i / 24, ch = i % 24;
        const int row = r0 + r;
        uint4 v = make_uint4(0u, 0u, 0u, 0u);
        if (row < N) {
            if (ch < NCHH) v = za[(size_t)row * NCHH + ch];
            else           v = zb[(size_t)row * NCHH + (ch - NCHH)];
        }
        zsb[r * 25 + ch] = v;
    }

    // B fragments: fully coalesced lane-major loads
    unsigned bf[12][2];
#pragma unroll
    for (int s = 0; s < 12; s++) {
        bf[s][0] = g_W3f[((j * 12 + s) * 2 + 0) * 32 + lane];
        bf[s][1] = g_W3f[((j * 12 + s) * 2 + 1) * 32 + lane];
    }
    const float2 sv = *reinterpret_cast<const float2*>(g_s3 + c0);
    const float2 cv = *reinterpret_cast<const float2*>(g_c3 + c0);
    __syncthreads();

    float d0 = 0.f, d1 = 0.f, d2 = 0.f, d3 = 0.f;
    const __half* base = zs + (rs * 16) * ZST;
#pragma unroll
    for (int s = 0; s < 12; s++) {
        const int ko = 2 * t + 16 * s;
        unsigned a0 = *reinterpret_cast<const unsigned*>(base + g * ZST + ko);
        unsigned a1 = *reinterpret_cast<const unsigned*>(base + (g + 8) * ZST + ko);
        unsigned a2 = *reinterpret_cast<const unsigned*>(base + g * ZST + ko + 8);
        unsigned a3 = *reinterpret_cast<const unsigned*>(base + (g + 8) * ZST + ko + 8);
        mma16816(d0, d1, d2, d3, a0, a1, a2, a3, bf[s][0], bf[s][1]);
    }

    const int rlo = r0 + rs * 16 + g;
    const int rhi = rlo + 8;
    if (rlo < N) {
        const float2 fi = *reinterpret_cast<const float2*>(feats + rlo * COUT + c0);
        float2 o;
        o.x = fmaf(d0, sv.x, cv.x) + fi.x;
        o.y = fmaf(d1, sv.y, cv.y) + fi.y;
        *reinterpret_cast<float2*>(out + rlo * COUT + c0) = o;
    }
    if (rhi < N) {
        const float2 fi = *reinterpret_cast<const float2*>(feats + rhi * COUT + c0);
        float2 o;
        o.x = fmaf(d2, sv.x, cv.x) + fi.x;
        o.y = fmaf(d3, sv.y, cv.y) + fi.y;
        *reinterpret_cast<float2*>(out + rhi * COUT + c0) = o;
    }
}

// ---------------------------------------------------------------------------
extern "C" void kernel_launch(void* const* d_in, const int* in_sizes, int n_in,
                              void* d_out, int out_size)
{
    const float* feats = (const float*)d_in[0];
    const int*   nbr   = (const int*)  d_in[1];
    const float* W1    = (const float*)d_in[2];
    const float* W2    = (const float*)d_in[3];
    const float* W3    = (const float*)d_in[4];
    const float* g1 = (const float*)d_in[5],  *b1 = (const float*)d_in[6];
    const float* m1 = (const float*)d_in[7],  *v1 = (const float*)d_in[8];
    const float* g2 = (const float*)d_in[9],  *b2 = (const float*)d_in[10];
    const float* m2 = (const float*)d_in[11], *v2 = (const float*)d_in[12];
    const float* g3 = (const float*)d_in[13], *b3 = (const float*)d_in[14];
    const float* m3 = (const float*)d_in[15], *v3 = (const float*)d_in[16];
    float* out = (float*)d_out;

    int N = in_sizes[0] / CIN;
    if (N > MAXN) N = MAXN;

    const int tiles = (N + 63) / 64;

    // K0: weight packing + BN fold
    k_prep<<<1, 768>>>(W1, W3, g1, b1, m1, v1, g2, b2, m2, v2, g3, b3, m3, v3);

    // K1: expand (MMA)
    k_expand<<<tiles, 768>>>(feats, N);

    // K2: depthwise gather, two channel-half passes (L2-resident each)
    const int grid2 = (N * NCHH + 255) / 256;
    k_dw_half<0><<<grid2, 256>>>(nbr, W2, N);
    k_dw_half<1><<<grid2, 256>>>(nbr, W2, N);

    // K3: project + residual (MMA)
    k_proj<<<tiles, 512>>>(feats, out, N);
}

// round 13
// speedup vs baseline: 1.1504x; 1.1504x over previous
#include <cuda_runtime.h>
#include <cuda_fp16.h>

#define MAXN   200000
#define CIN    32
#define HID    192
#define KOFF   9
#define COUT   32
#define EPSV   1e-5f

// fp16 scratch: expanded activations x1 = relu6(bn1(feats@W1)) [N,192].
// 76.8MB -> largely L2-resident (126MB L2); with dw+proj fused there is no
// competing z stream, so the random gather mostly hits L2.
__device__ __half g_x1[(size_t)MAXN * HID];

// prep-kernel outputs: fragment-packed weights + folded BN constants
__device__ unsigned g_W1f[24 * 2 * 2 * 32];   // [w][s][i][lane]
__device__ unsigned g_W3f[4 * 12 * 2 * 32];   // [j][s][i][lane]
__device__ float g_s1[HID], g_c1[HID];
__device__ float g_s2[HID], g_c2[HID];
__device__ float g_s3[COUT], g_c3[COUT];

__device__ __forceinline__ float relu6f(float x) {
    return fminf(fmaxf(x, 0.0f), 6.0f);
}
__device__ __forceinline__ float2 h2tof2(unsigned int u) {
    __half2 h = *reinterpret_cast<__half2*>(&u);
    return __half22float2(h);
}
__device__ __forceinline__ unsigned int f2toh2(float a, float b) {
    __half2 h = __floats2half2_rn(a, b);
    return *reinterpret_cast<unsigned int*>(&h);
}
__device__ __forceinline__ unsigned int packh(__half lo, __half hi) {
    __half2 h = __halves2half2(lo, hi);
    return *reinterpret_cast<unsigned int*>(&h);
}

// m16n8k16 fp16 x fp16 -> fp32 MMA
__device__ __forceinline__ void mma16816(
    float& d0, float& d1, float& d2, float& d3,
    unsigned a0, unsigned a1, unsigned a2, unsigned a3,
    unsigned b0, unsigned b1)
{
    asm volatile(
        "mma.sync.aligned.m16n8k16.row.col.f32.f16.f16.f32 "
        "{%0,%1,%2,%3}, {%4,%5,%6,%7}, {%8,%9}, {%0,%1,%2,%3};\n"
        : "+f"(d0), "+f"(d1), "+f"(d2), "+f"(d3)
        : "r"(a0), "r"(a1), "r"(a2), "r"(a3), "r"(b0), "r"(b1));
}

// ---------------------------------------------------------------------------
// Prep: pack W1/W3 into fragment-ready lane-major arrays, fold BN constants.
// One block, 768 threads, ~2us.
// ---------------------------------------------------------------------------
__global__ void __launch_bounds__(768) k_prep(
    const float* __restrict__ W1, const float* __restrict__ W3,
    const float* __restrict__ g1, const float* __restrict__ b1,
    const float* __restrict__ m1, const float* __restrict__ v1,
    const float* __restrict__ g2, const float* __restrict__ b2,
    const float* __restrict__ m2, const float* __restrict__ v2,
    const float* __restrict__ g3, const float* __restrict__ b3,
    const float* __restrict__ m3, const float* __restrict__ v3)
{
    const int tid  = threadIdx.x;
    const int lane = tid & 31;
    const int g    = lane >> 2;
    const int t    = lane & 3;

    // W1 fragments: 24 warp-tiles x 2 k-steps x 2 regs
    {
        const int w = tid >> 5;           // 0..23
        const int col = w * 8 + g;
#pragma unroll
        for (int s = 0; s < 2; s++)
#pragma unroll
            for (int i = 0; i < 2; i++) {
                const int k0 = 16 * s + 2 * t + 8 * i;
                g_W1f[((w * 2 + s) * 2 + i) * 32 + lane] =
                    packh(__float2half(W1[(k0)     * HID + col]),
                          __float2half(W1[(k0 + 1) * HID + col]));
            }
    }
    // W3 fragments: 4 n-tiles x 12 k-steps x 2 regs
    if (tid < 128) {
        const int j = tid >> 5;           // 0..3
        const int col = j * 8 + g;
#pragma unroll
        for (int s = 0; s < 12; s++)
#pragma unroll
            for (int i = 0; i < 2; i++) {
                const int k0 = 16 * s + 2 * t + 8 * i;
                g_W3f[((j * 12 + s) * 2 + i) * 32 + lane] =
                    packh(__float2half(W3[(k0)     * COUT + col]),
                          __float2half(W3[(k0 + 1) * COUT + col]));
            }
    }
    if (tid < HID) {
        float s = g1[tid] * rsqrtf(v1[tid] + EPSV);
        g_s1[tid] = s; g_c1[tid] = b1[tid] - m1[tid] * s;
        s = g2[tid] * rsqrtf(v2[tid] + EPSV);
        g_s2[tid] = s; g_c2[tid] = b2[tid] - m2[tid] * s;
    }
    if (tid < COUT) {
        const float s = g3[tid] * rsqrtf(v3[tid] + EPSV);
        g_s3[tid] = s; g_c3[tid] = b3[tid] - m3[tid] * s;
    }
}

// ---------------------------------------------------------------------------
// Kernel 1 (MMA): expand 1x1 conv + BN1 + relu6 -> g_x1 (fp16)
// Block = 768 thr = 24 warps; warp w owns output cols [8w, 8w+8).
// 64-row tile; feats staged fp16 in smem (stride 40 halves, conflict-free).
// ---------------------------------------------------------------------------
#define FST   40
#define XST   208   // epilogue smem stride (halves) = 26 uint4

__global__ void __launch_bounds__(768) k_expand(
    const float* __restrict__ feats, int N)
{
    __shared__ __align__(16) __half sf[64 * FST];
    __shared__ __align__(16) __half sx[64 * XST];

    const int tid  = threadIdx.x;
    const int w    = tid >> 5;
    const int lane = tid & 31;
    const int g    = lane >> 2;
    const int t    = lane & 3;
    const int colb = w * 8;
    const int c0   = colb + 2 * t;

    unsigned bf[2][2];
#pragma unroll
    for (int s = 0; s < 2; s++)
#pragma unroll
        for (int i = 0; i < 2; i++)
            bf[s][i] = g_W1f[((w * 2 + s) * 2 + i) * 32 + lane];

    const float2 sv = *reinterpret_cast<const float2*>(g_s1 + c0);
    const float2 cv = *reinterpret_cast<const float2*>(g_c1 + c0);

    const int r0 = blockIdx.x * 64;

#pragma unroll
    for (int i = tid; i < 64 * CIN; i += 768) {
        const int r = i >> 5, c = i & 31;
        const int row = r0 + r;
        const float v = (row < N) ? feats[row * CIN + c] : 0.0f;
        sf[r * FST + c] = __float2half(v);
    }
    __syncthreads();

#pragma unroll
    for (int sub = 0; sub < 4; sub++) {
        float d0 = 0.f, d1 = 0.f, d2 = 0.f, d3 = 0.f;
        const __half* base = sf + (sub * 16) * FST;
#pragma unroll
        for (int s = 0; s < 2; s++) {
            const int ko = 2 * t + 16 * s;
            unsigned a0 = *reinterpret_cast<const unsigned*>(base + g * FST + ko);
            unsigned a1 = *reinterpret_cast<const unsigned*>(base + (g + 8) * FST + ko);
            unsigned a2 = *reinterpret_cast<const unsigned*>(base + g * FST + ko + 8);
            unsigned a3 = *reinterpret_cast<const unsigned*>(base + (g + 8) * FST + ko + 8);
            mma16816(d0, d1, d2, d3, a0, a1, a2, a3, bf[s][0], bf[s][1]);
        }
        const int rlo = sub * 16 + g;
        const int rhi = rlo + 8;
        *reinterpret_cast<unsigned*>(sx + rlo * XST + c0) =
            f2toh2(relu6f(fmaf(d0, sv.x, cv.x)), relu6f(fmaf(d1, sv.y, cv.y)));
        *reinterpret_cast<unsigned*>(sx + rhi * XST + c0) =
            f2toh2(relu6f(fmaf(d2, sv.x, cv.x)), relu6f(fmaf(d3, sv.y, cv.y)));
    }
    __syncthreads();

    // coalesced store: 64 rows x 24 uint4
    uint4* xg = reinterpret_cast<uint4*>(g_x1);
    const uint4* sxb = reinterpret_cast<const uint4*>(sx);
#pragma unroll
    for (int i = tid; i < 64 * 24; i += 768) {
        const int r = i / 24, ch = i % 24;
        const int row = r0 + r;
        if (row < N) xg[(size_t)row * 24 + ch] = sxb[r * 26 + ch];
    }
}

// ---------------------------------------------------------------------------
// Kernel 2 (FUSED): depthwise sparse conv + BN2 + relu6 -> smem tile ->
// project MMA + BN3 + residual -> out (fp32). z never touches gmem.
//
// Gather phase: 64 rows x 24 chunks = 1536 items, 3 per thread. Items are
// mapped so each 8-lane group covers one 128B-ALIGNED segment of one
// neighbor row (row base = id*384B; segment = 0/128/256B): a warp-gather is
// 4 random lines, 1 L1 wavefront each — minimal wavefronts, and L2 sees one
// 128B access per line. nbr tile staged in smem (coalesced, once per block).
//
// MMA phase: identical to prior k_proj (ZST=200 conflict-free staging, W3
// fragments coalesced from g_W3f, BN3 + fp32 residual epilogue).
// ---------------------------------------------------------------------------
#define ZST 200   // halves; 25 uint4 per row

__global__ void __launch_bounds__(512) k_dwproj(
    const int* __restrict__ nbr, const float* __restrict__ W2,
    const float* __restrict__ feats, float* __restrict__ out, int N)
{
    __shared__ __align__(16) __half zs[64 * ZST];       // 25.6 KB
    __shared__ __align__(16) float W2s[KOFF * HID];     // 6.9 KB
    __shared__ __align__(16) int   nbs[64 * KOFF];      // 2.3 KB

    const int tid  = threadIdx.x;
    const int lane = tid & 31;
    const int w    = tid >> 5;
    const int r0   = blockIdx.x * 64;

    // stage W2 (k-major [K,HID]) and the nbr tile
    for (int i = tid; i < KOFF * HID; i += 512) W2s[i] = W2[i];
    for (int i = tid; i < 64 * KOFF; i += 512) {
        const int row = r0 + i / KOFF;
        nbs[i] = (row < N) ? nbr[row * KOFF + (i % KOFF)] : -1;
    }
    __syncthreads();

    // ---- gather + BN2 + relu6 -> zs ----
    const uint4* xg = reinterpret_cast<const uint4*>(g_x1);
    uint4* zsb = reinterpret_cast<uint4*>(zs);

#pragma unroll
    for (int it = 0; it < 3; it++) {
        const int i    = tid + it * 512;
        const int grpI = i >> 3;            // 0..191 : (row, 128B segment)
        const int l    = i & 7;
        const int rloc = grpI / 3;
        const int seg  = grpI % 3;
        const int ch   = seg * 8 + l;       // uint4 chunk 0..23
        const int ch8  = ch * 8;            // first channel

        int ids[KOFF];
#pragma unroll
        for (int k = 0; k < KOFF; k++) ids[k] = nbs[rloc * KOFF + k];

        uint4 v[KOFF];
#pragma unroll
        for (int k = 0; k < KOFF; k++) {
            v[k] = make_uint4(0u, 0u, 0u, 0u);
            if (ids[k] >= 0) v[k] = xg[(size_t)ids[k] * 24 + ch];
        }

        float a0 = 0.f, a1 = 0.f, a2 = 0.f, a3 = 0.f;
        float a4 = 0.f, a5 = 0.f, a6 = 0.f, a7 = 0.f;
#pragma unroll
        for (int k = 0; k < KOFF; k++) {
            const float4 wA = *reinterpret_cast<const float4*>(W2s + k * HID + ch8);
            const float4 wB = *reinterpret_cast<const float4*>(W2s + k * HID + ch8 + 4);
            const float2 f0 = h2tof2(v[k].x);
            const float2 f1 = h2tof2(v[k].y);
            const float2 f2 = h2tof2(v[k].z);
            const float2 f3 = h2tof2(v[k].w);
            a0 = fmaf(f0.x, wA.x, a0);
            a1 = fmaf(f0.y, wA.y, a1);
            a2 = fmaf(f1.x, wA.z, a2);
            a3 = fmaf(f1.y, wA.w, a3);
            a4 = fmaf(f2.x, wB.x, a4);
            a5 = fmaf(f2.y, wB.y, a5);
            a6 = fmaf(f3.x, wB.z, a6);
            a7 = fmaf(f3.y, wB.w, a7);
        }

        const float4 sA = *reinterpret_cast<const float4*>(g_s2 + ch8);
        const float4 sB = *reinterpret_cast<const float4*>(g_s2 + ch8 + 4);
        const float4 cA = *reinterpret_cast<const float4*>(g_c2 + ch8);
        const float4 cB = *reinterpret_cast<const float4*>(g_c2 + ch8 + 4);

        uint4 o;
        o.x = f2toh2(relu6f(fmaf(a0, sA.x, cA.x)), relu6f(fmaf(a1, sA.y, cA.y)));
        o.y = f2toh2(relu6f(fmaf(a2, sA.z, cA.z)), relu6f(fmaf(a3, sA.w, cA.w)));
        o.z = f2toh2(relu6f(fmaf(a4, sB.x, cB.x)), relu6f(fmaf(a5, sB.y, cB.y)));
        o.w = f2toh2(relu6f(fmaf(a6, sB.z, cB.z)), relu6f(fmaf(a7, sB.w, cB.w)));
        zsb[rloc * 25 + ch] = o;
    }

    // ---- project MMA + BN3 + residual ----
    const int g  = lane >> 2;
    const int t  = lane & 3;
    const int j  = w & 3;                  // n-tile
    const int rs = w >> 2;                 // row subtile
    const int c0 = 8 * j + 2 * t;

    unsigned bf[12][2];
#pragma unroll
    for (int s = 0; s < 12; s++) {
        bf[s][0] = g_W3f[((j * 12 + s) * 2 + 0) * 32 + lane];
        bf[s][1] = g_W3f[((j * 12 + s) * 2 + 1) * 32 + lane];
    }
    const float2 sv = *reinterpret_cast<const float2*>(g_s3 + c0);
    const float2 cv = *reinterpret_cast<const float2*>(g_c3 + c0);
    __syncthreads();

    float d0 = 0.f, d1 = 0.f, d2 = 0.f, d3 = 0.f;
    const __half* base = zs + (rs * 16) * ZST;
#pragma unroll
    for (int s = 0; s < 12; s++) {
        const int ko = 2 * t + 16 * s;
        unsigned a0 = *reinterpret_cast<const unsigned*>(base + g * ZST + ko);
        unsigned a1 = *reinterpret_cast<const unsigned*>(base + (g + 8) * ZST + ko);
        unsigned a2 = *reinterpret_cast<const unsigned*>(base + g * ZST + ko + 8);
        unsigned a3 = *reinterpret_cast<const unsigned*>(base + (g + 8) * ZST + ko + 8);
        mma16816(d0, d1, d2, d3, a0, a1, a2, a3, bf[s][0], bf[s][1]);
    }

    const int rlo = r0 + rs * 16 + g;
    const int rhi = rlo + 8;
    if (rlo < N) {
        const float2 fi = *reinterpret_cast<const float2*>(feats + rlo * COUT + c0);
        float2 o;
        o.x = fmaf(d0, sv.x, cv.x) + fi.x;
        o.y = fmaf(d1, sv.y, cv.y) + fi.y;
        *reinterpret_cast<float2*>(out + rlo * COUT + c0) = o;
    }
    if (rhi < N) {
        const float2 fi = *reinterpret_cast<const float2*>(feats + rhi * COUT + c0);
        float2 o;
        o.x = fmaf(d2, sv.x, cv.x) + fi.x;
        o.y = fmaf(d3, sv.y, cv.y) + fi.y;
        *reinterpret_cast<float2*>(out + rhi * COUT + c0) = o;
    }
}

// ---------------------------------------------------------------------------
extern "C" void kernel_launch(void* const* d_in, const int* in_sizes, int n_in,
                              void* d_out, int out_size)
{
    const float* feats = (const float*)d_in[0];
    const int*   nbr   = (const int*)  d_in[1];
    const float* W1    = (const float*)d_in[2];
    const float* W2    = (const float*)d_in[3];
    const float* W3    = (const float*)d_in[4];
    const float* g1 = (const float*)d_in[5],  *b1 = (const float*)d_in[6];
    const float* m1 = (const float*)d_in[7],  *v1 = (const float*)d_in[8];
    const float* g2 = (const float*)d_in[9],  *b2 = (const float*)d_in[10];
    const float* m2 = (const float*)d_in[11], *v2 = (const float*)d_in[12];
    const float* g3 = (const float*)d_in[13], *b3 = (const float*)d_in[14];
    const float* m3 = (const float*)d_in[15], *v3 = (const float*)d_in[16];
    float* out = (float*)d_out;

    int N = in_sizes[0] / CIN;
    if (N > MAXN) N = MAXN;

    const int tiles = (N + 63) / 64;

    // K0: weight packing + BN fold
    k_prep<<<1, 768>>>(W1, W3, g1, b1, m1, v1, g2, b2, m2, v2, g3, b3, m3, v3);

    // K1: expand (MMA)
    k_expand<<<tiles, 768>>>(feats, N);

    // K2: fused depthwise gather + project (MMA) + residual
    k_dwproj<<<tiles, 512>>>(nbr, W2, feats, out, N);
}

// round 14
// speedup vs baseline: 1.6765x; 1.4573x over previous
#include <cuda_runtime.h>
#include <cuda_fp16.h>

#define MAXN   200000
#define CIN    32
#define HID    192
#define KOFF   9
#define COUT   32
#define EPSV   1e-5f

// fp16 scratch: expanded activations x1 = relu6(bn1(feats@W1)) [N,192].
// 76.8MB -> largely L2-resident (126MB L2); dw+proj fused so no z stream.
__device__ __half g_x1[(size_t)MAXN * HID];

// prep-kernel outputs: fragment-packed weights + folded BN constants
__device__ unsigned g_W1f[24 * 2 * 2 * 32];   // [w][s][i][lane]
__device__ unsigned g_W3f[4 * 12 * 2 * 32];   // [j][s][i][lane]
__device__ float g_s1[HID], g_c1[HID];
__device__ float g_s3[COUT], g_c3[COUT];
// half-precision dw constants (native half2 datapath in the gather phase)
__device__ __align__(16) __half g_W2h[KOFF * HID];
__device__ __align__(16) __half g_s2h[HID];
__device__ __align__(16) __half g_c2h[HID];

__device__ __forceinline__ float relu6f(float x) {
    return fminf(fmaxf(x, 0.0f), 6.0f);
}
__device__ __forceinline__ unsigned int f2toh2(float a, float b) {
    __half2 h = __floats2half2_rn(a, b);
    return *reinterpret_cast<unsigned int*>(&h);
}
__device__ __forceinline__ unsigned int packh(__half lo, __half hi) {
    __half2 h = __halves2half2(lo, hi);
    return *reinterpret_cast<unsigned int*>(&h);
}
__device__ __forceinline__ __half2 u2h2(unsigned u) {
    return *reinterpret_cast<__half2*>(&u);
}
__device__ __forceinline__ unsigned h2u(__half2 h) {
    return *reinterpret_cast<unsigned*>(&h);
}

// m16n8k16 fp16 x fp16 -> fp32 MMA
__device__ __forceinline__ void mma16816(
    float& d0, float& d1, float& d2, float& d3,
    unsigned a0, unsigned a1, unsigned a2, unsigned a3,
    unsigned b0, unsigned b1)
{
    asm volatile(
        "mma.sync.aligned.m16n8k16.row.col.f32.f16.f16.f32 "
        "{%0,%1,%2,%3}, {%4,%5,%6,%7}, {%8,%9}, {%0,%1,%2,%3};\n"
        : "+f"(d0), "+f"(d1), "+f"(d2), "+f"(d3)
        : "r"(a0), "r"(a1), "r"(a2), "r"(a3), "r"(b0), "r"(b1));
}

// ---------------------------------------------------------------------------
// Prep (parallel, 32 blocks x 128 thr): pack W1/W3 fragments, convert W2/BN2
// to half, fold BN constants. ~2.5us.
// ---------------------------------------------------------------------------
__global__ void __launch_bounds__(128) k_prep(
    const float* __restrict__ W1, const float* __restrict__ W2,
    const float* __restrict__ W3,
    const float* __restrict__ g1, const float* __restrict__ b1,
    const float* __restrict__ m1, const float* __restrict__ v1,
    const float* __restrict__ g2, const float* __restrict__ b2,
    const float* __restrict__ m2, const float* __restrict__ v2,
    const float* __restrict__ g3, const float* __restrict__ b3,
    const float* __restrict__ m3, const float* __restrict__ v3)
{
    const int b    = blockIdx.x;
    const int tid  = threadIdx.x;
    const int lane = tid & 31;
    const int g    = lane >> 2;
    const int t    = lane & 3;

    if (b < 24) {                 // W1 fragments, tile w = b
        if (tid < 32) {
            const int col = b * 8 + g;
#pragma unroll
            for (int s = 0; s < 2; s++)
#pragma unroll
                for (int i = 0; i < 2; i++) {
                    const int k0 = 16 * s + 2 * t + 8 * i;
                    g_W1f[((b * 2 + s) * 2 + i) * 32 + lane] =
                        packh(__float2half(W1[(k0)     * HID + col]),
                              __float2half(W1[(k0 + 1) * HID + col]));
                }
        }
    } else if (b < 28) {          // W3 fragments, tile j = b-24
        if (tid < 32) {
            const int j = b - 24;
            const int col = j * 8 + g;
#pragma unroll
            for (int s = 0; s < 12; s++)
#pragma unroll
                for (int i = 0; i < 2; i++) {
                    const int k0 = 16 * s + 2 * t + 8 * i;
                    g_W3f[((j * 12 + s) * 2 + i) * 32 + lane] =
                        packh(__float2half(W3[(k0)     * COUT + col]),
                              __float2half(W3[(k0 + 1) * COUT + col]));
                }
        }
    } else if (b == 28) {         // BN1 fold (fp32)
        for (int i = tid; i < HID; i += 128) {
            const float s = g1[i] * rsqrtf(v1[i] + EPSV);
            g_s1[i] = s; g_c1[i] = b1[i] - m1[i] * s;
        }
    } else if (b == 29) {         // BN2 fold (fp16)
        for (int i = tid; i < HID; i += 128) {
            const float s = g2[i] * rsqrtf(v2[i] + EPSV);
            g_s2h[i] = __float2half(s);
            g_c2h[i] = __float2half(b2[i] - m2[i] * s);
        }
    } else if (b == 30) {         // W2 -> half (same [K][HID] layout)
        for (int i = tid; i < KOFF * HID; i += 128)
            g_W2h[i] = __float2half(W2[i]);
    } else {                      // BN3 fold (fp32)
        for (int i = tid; i < COUT; i += 128) {
            const float s = g3[i] * rsqrtf(v3[i] + EPSV);
            g_s3[i] = s; g_c3[i] = b3[i] - m3[i] * s;
        }
    }
}

// ---------------------------------------------------------------------------
// Kernel 1 (MMA): expand 1x1 conv + BN1 + relu6 -> g_x1 (fp16)
// Block = 768 thr = 24 warps; warp w owns output cols [8w, 8w+8).
// 64-row tile; feats staged fp16 in smem (stride 40 halves, conflict-free).
// ---------------------------------------------------------------------------
#define FST   40
#define XST   208   // epilogue smem stride (halves) = 26 uint4

__global__ void __launch_bounds__(768) k_expand(
    const float* __restrict__ feats, int N)
{
    __shared__ __align__(16) __half sf[64 * FST];
    __shared__ __align__(16) __half sx[64 * XST];

    const int tid  = threadIdx.x;
    const int w    = tid >> 5;
    const int lane = tid & 31;
    const int g    = lane >> 2;
    const int t    = lane & 3;
    const int colb = w * 8;
    const int c0   = colb + 2 * t;

    unsigned bf[2][2];
#pragma unroll
    for (int s = 0; s < 2; s++)
#pragma unroll
        for (int i = 0; i < 2; i++)
            bf[s][i] = g_W1f[((w * 2 + s) * 2 + i) * 32 + lane];

    const float2 sv = *reinterpret_cast<const float2*>(g_s1 + c0);
    const float2 cv = *reinterpret_cast<const float2*>(g_c1 + c0);

    const int r0 = blockIdx.x * 64;

#pragma unroll
    for (int i = tid; i < 64 * CIN; i += 768) {
        const int r = i >> 5, c = i & 31;
        const int row = r0 + r;
        const float v = (row < N) ? feats[row * CIN + c] : 0.0f;
        sf[r * FST + c] = __float2half(v);
    }
    __syncthreads();

#pragma unroll
    for (int sub = 0; sub < 4; sub++) {
        float d0 = 0.f, d1 = 0.f, d2 = 0.f, d3 = 0.f;
        const __half* base = sf + (sub * 16) * FST;
#pragma unroll
        for (int s = 0; s < 2; s++) {
            const int ko = 2 * t + 16 * s;
            unsigned a0 = *reinterpret_cast<const unsigned*>(base + g * FST + ko);
            unsigned a1 = *reinterpret_cast<const unsigned*>(base + (g + 8) * FST + ko);
            unsigned a2 = *reinterpret_cast<const unsigned*>(base + g * FST + ko + 8);
            unsigned a3 = *reinterpret_cast<const unsigned*>(base + (g + 8) * FST + ko + 8);
            mma16816(d0, d1, d2, d3, a0, a1, a2, a3, bf[s][0], bf[s][1]);
        }
        const int rlo = sub * 16 + g;
        const int rhi = rlo + 8;
        *reinterpret_cast<unsigned*>(sx + rlo * XST + c0) =
            f2toh2(relu6f(fmaf(d0, sv.x, cv.x)), relu6f(fmaf(d1, sv.y, cv.y)));
        *reinterpret_cast<unsigned*>(sx + rhi * XST + c0) =
            f2toh2(relu6f(fmaf(d2, sv.x, cv.x)), relu6f(fmaf(d3, sv.y, cv.y)));
    }
    __syncthreads();

    // coalesced store: 64 rows x 24 uint4
    uint4* xg = reinterpret_cast<uint4*>(g_x1);
    const uint4* sxb = reinterpret_cast<const uint4*>(sx);
#pragma unroll
    for (int i = tid; i < 64 * 24; i += 768) {
        const int r = i / 24, ch = i % 24;
        const int row = r0 + r;
        if (row < N) xg[(size_t)row * 24 + ch] = sxb[r * 26 + ch];
    }
}

// ---------------------------------------------------------------------------
// Kernel 2 (FUSED): depthwise gather (half2 datapath) + BN2 + relu6 -> smem
// tile -> project MMA + BN3 + residual -> out (fp32).
//
// Gather: 64 rows x 24 chunks, 3 items/thread; each 8-lane group covers one
// 128B-aligned segment of one neighbor row (1 line / group). Depthwise
// multiply-accumulate entirely in HFMA2 on packed half2 (no cvt), W2 + BN2
// constants pre-converted to fp16 in prep.
// ---------------------------------------------------------------------------
#define ZST 200   // halves; 25 uint4 per row

__global__ void __launch_bounds__(512, 2) k_dwproj(
    const int* __restrict__ nbr,
    const float* __restrict__ feats, float* __restrict__ out, int N)
{
    __shared__ __align__(16) __half zs[64 * ZST];       // 25.6 KB
    __shared__ __align__(16) __half W2s[KOFF * HID];    // 3.4 KB
    __shared__ __align__(16) __half s2s[HID];
    __shared__ __align__(16) __half c2s[HID];
    __shared__ __align__(16) int    nbs[64 * KOFF];     // 2.3 KB

    const int tid  = threadIdx.x;
    const int lane = tid & 31;
    const int w    = tid >> 5;
    const int r0   = blockIdx.x * 64;

    // stage half W2 / BN2 (uint4 copies) and the nbr tile
    {
        const uint4* src = reinterpret_cast<const uint4*>(g_W2h);
        uint4* dst = reinterpret_cast<uint4*>(W2s);
        for (int i = tid; i < KOFF * HID / 8; i += 512) dst[i] = src[i];
        if (tid < HID / 8) {
            reinterpret_cast<uint4*>(s2s)[tid] =
                reinterpret_cast<const uint4*>(g_s2h)[tid];
            reinterpret_cast<uint4*>(c2s)[tid] =
                reinterpret_cast<const uint4*>(g_c2h)[tid];
        }
    }
    for (int i = tid; i < 64 * KOFF; i += 512) {
        const int row = r0 + i / KOFF;
        nbs[i] = (row < N) ? nbr[row * KOFF + (i % KOFF)] : -1;
    }
    __syncthreads();

    // ---- gather + depthwise (half2) + BN2 + relu6 -> zs ----
    const uint4* xg = reinterpret_cast<const uint4*>(g_x1);
    uint4* zsb = reinterpret_cast<uint4*>(zs);
    const __half2 zero2 = __floats2half2_rn(0.f, 0.f);
    const __half2 six2  = __floats2half2_rn(6.f, 6.f);

#pragma unroll
    for (int it = 0; it < 3; it++) {
        const int i    = tid + it * 512;
        const int grpI = i >> 3;            // (row, 128B segment)
        const int l    = i & 7;
        const int rloc = grpI / 3;
        const int seg  = grpI % 3;
        const int ch   = seg * 8 + l;       // uint4 chunk 0..23
        const int ch8  = ch * 8;            // first channel (half index)

        int ids[KOFF];
#pragma unroll
        for (int k = 0; k < KOFF; k++) ids[k] = nbs[rloc * KOFF + k];

        uint4 v[KOFF];
#pragma unroll
        for (int k = 0; k < KOFF; k++) {
            v[k] = make_uint4(0u, 0u, 0u, 0u);
            if (ids[k] >= 0) v[k] = xg[(size_t)ids[k] * 24 + ch];
        }

        __half2 a0 = zero2, a1 = zero2, a2 = zero2, a3 = zero2;
#pragma unroll
        for (int k = 0; k < KOFF; k++) {
            const uint4 wv = *reinterpret_cast<const uint4*>(W2s + k * HID + ch8);
            a0 = __hfma2(u2h2(v[k].x), u2h2(wv.x), a0);
            a1 = __hfma2(u2h2(v[k].y), u2h2(wv.y), a1);
            a2 = __hfma2(u2h2(v[k].z), u2h2(wv.z), a2);
            a3 = __hfma2(u2h2(v[k].w), u2h2(wv.w), a3);
        }

        const uint4 sv4 = *reinterpret_cast<const uint4*>(s2s + ch8);
        const uint4 cv4 = *reinterpret_cast<const uint4*>(c2s + ch8);
        uint4 o;
        o.x = h2u(__hmin2(six2, __hmax2(zero2, __hfma2(a0, u2h2(sv4.x), u2h2(cv4.x)))));
        o.y = h2u(__hmin2(six2, __hmax2(zero2, __hfma2(a1, u2h2(sv4.y), u2h2(cv4.y)))));
        o.z = h2u(__hmin2(six2, __hmax2(zero2, __hfma2(a2, u2h2(sv4.z), u2h2(cv4.z)))));
        o.w = h2u(__hmin2(six2, __hmax2(zero2, __hfma2(a3, u2h2(sv4.w), u2h2(cv4.w)))));
        zsb[rloc * 25 + ch] = o;
    }

    // ---- project MMA + BN3 + residual ----
    const int g  = lane >> 2;
    const int t  = lane & 3;
    const int j  = w & 3;                  // n-tile
    const int rs = w >> 2;                 // row subtile
    const int c0 = 8 * j + 2 * t;

    unsigned bf[12][2];
#pragma unroll
    for (int s = 0; s < 12; s++) {
        bf[s][0] = g_W3f[((j * 12 + s) * 2 + 0) * 32 + lane];
        bf[s][1] = g_W3f[((j * 12 + s) * 2 + 1) * 32 + lane];
    }
    const float2 sv = *reinterpret_cast<const float2*>(g_s3 + c0);
    const float2 cv = *reinterpret_cast<const float2*>(g_c3 + c0);
    __syncthreads();

    float d0 = 0.f, d1 = 0.f, d2 = 0.f, d3 = 0.f;
    const __half* base = zs + (rs * 16) * ZST;
#pragma unroll
    for (int s = 0; s < 12; s++) {
        const int ko = 2 * t + 16 * s;
        unsigned a0 = *reinterpret_cast<const unsigned*>(base + g * ZST + ko);
        unsigned a1 = *reinterpret_cast<const unsigned*>(base + (g + 8) * ZST + ko);
        unsigned a2 = *reinterpret_cast<const unsigned*>(base + g * ZST + ko + 8);
        unsigned a3 = *reinterpret_cast<const unsigned*>(base + (g + 8) * ZST + ko + 8);
        mma16816(d0, d1, d2, d3, a0, a1, a2, a3, bf[s][0], bf[s][1]);
    }

    const int rlo = r0 + rs * 16 + g;
    const int rhi = rlo + 8;
    if (rlo < N) {
        const float2 fi = *reinterpret_cast<const float2*>(feats + rlo * COUT + c0);
        float2 o;
        o.x = fmaf(d0, sv.x, cv.x) + fi.x;
        o.y = fmaf(d1, sv.y, cv.y) + fi.y;
        *reinterpret_cast<float2*>(out + rlo * COUT + c0) = o;
    }
    if (rhi < N) {
        const float2 fi = *reinterpret_cast<const float2*>(feats + rhi * COUT + c0);
        float2 o;
        o.x = fmaf(d2, sv.x, cv.x) + fi.x;
        o.y = fmaf(d3, sv.y, cv.y) + fi.y;
        *reinterpret_cast<float2*>(out + rhi * COUT + c0) = o;
    }
}

// ---------------------------------------------------------------------------
extern "C" void kernel_launch(void* const* d_in, const int* in_sizes, int n_in,
                              void* d_out, int out_size)
{
    const float* feats = (const float*)d_in[0];
    const int*   nbr   = (const int*)  d_in[1];
    const float* W1    = (const float*)d_in[2];
    const float* W2    = (const float*)d_in[3];
    const float* W3    = (const float*)d_in[4];
    const float* g1 = (const float*)d_in[5],  *b1 = (const float*)d_in[6];
    const float* m1 = (const float*)d_in[7],  *v1 = (const float*)d_in[8];
    const float* g2 = (const float*)d_in[9],  *b2 = (const float*)d_in[10];
    const float* m2 = (const float*)d_in[11], *v2 = (const float*)d_in[12];
    const float* g3 = (const float*)d_in[13], *b3 = (const float*)d_in[14];
    const float* m3 = (const float*)d_in[15], *v3 = (const float*)d_in[16];
    float* out = (float*)d_out;

    int N = in_sizes[0] / CIN;
    if (N > MAXN) N = MAXN;

    const int tiles = (N + 63) / 64;

    // K0: weight packing + BN fold (parallel)
    k_prep<<<32, 128>>>(W1, W2, W3, g1, b1, m1, v1,
                        g2, b2, m2, v2, g3, b3, m3, v3);

    // K1: expand (MMA)
    k_expand<<<tiles, 768>>>(feats, N);

    // K2: fused depthwise gather (half2) + project (MMA) + residual
    k_dwproj<<<tiles, 512>>>(nbr, feats, out, N);
}

// round 15
// speedup vs baseline: 1.6836x; 1.0042x over previous
#include <cuda_runtime.h>
#include <cuda_fp16.h>

#define MAXN   200000
#define CIN    32
#define HID    192
#define KOFF   9
#define COUT   32
#define EPSV   1e-5f

// fp16 scratch: expanded activations x1 = relu6(bn1(feats@W1)) [N,192].
// 76.8MB -> largely L2-resident (126MB L2); dw+proj fused so no z stream.
__device__ __half g_x1[(size_t)MAXN * HID];

// prep-kernel outputs: fragment-packed weights + folded BN constants
__device__ unsigned g_W1f[24 * 2 * 2 * 32];   // [w][s][i][lane]
__device__ unsigned g_W3f[4 * 12 * 2 * 32];   // [j][s][i][lane]
__device__ float g_s1[HID], g_c1[HID];
__device__ float g_s3[COUT], g_c3[COUT];
// half-precision dw constants (native half2 datapath in the gather phase)
__device__ __align__(16) __half g_W2h[KOFF * HID];
__device__ __align__(16) __half g_s2h[HID];
__device__ __align__(16) __half g_c2h[HID];

__device__ __forceinline__ float relu6f(float x) {
    return fminf(fmaxf(x, 0.0f), 6.0f);
}
__device__ __forceinline__ unsigned int f2toh2(float a, float b) {
    __half2 h = __floats2half2_rn(a, b);
    return *reinterpret_cast<unsigned int*>(&h);
}
__device__ __forceinline__ unsigned int packh(__half lo, __half hi) {
    __half2 h = __halves2half2(lo, hi);
    return *reinterpret_cast<unsigned int*>(&h);
}
__device__ __forceinline__ __half2 u2h2(unsigned u) {
    return *reinterpret_cast<__half2*>(&u);
}
__device__ __forceinline__ unsigned h2u(__half2 h) {
    return *reinterpret_cast<unsigned*>(&h);
}

// m16n8k16 fp16 x fp16 -> fp32 MMA
__device__ __forceinline__ void mma16816(
    float& d0, float& d1, float& d2, float& d3,
    unsigned a0, unsigned a1, unsigned a2, unsigned a3,
    unsigned b0, unsigned b1)
{
    asm volatile(
        "mma.sync.aligned.m16n8k16.row.col.f32.f16.f16.f32 "
        "{%0,%1,%2,%3}, {%4,%5,%6,%7}, {%8,%9}, {%0,%1,%2,%3};\n"
        : "+f"(d0), "+f"(d1), "+f"(d2), "+f"(d3)
        : "r"(a0), "r"(a1), "r"(a2), "r"(a3), "r"(b0), "r"(b1));
}

// ldmatrix x4: loads the full m16n8k16 A fragment in one instruction.
// Lane addressing (set by caller): lanes 0-7 -> rows 0-7 @k0, 8-15 -> rows
// 8-15 @k0, 16-23 -> rows 0-7 @k0+8, 24-31 -> rows 8-15 @k0+8, so the four
// result regs are exactly (a0,a1,a2,a3).
__device__ __forceinline__ void ldsm_x4(
    unsigned& r0, unsigned& r1, unsigned& r2, unsigned& r3, unsigned addr)
{
    asm volatile(
        "ldmatrix.sync.aligned.m8n8.x4.shared.b16 {%0,%1,%2,%3}, [%4];\n"
        : "=r"(r0), "=r"(r1), "=r"(r2), "=r"(r3) : "r"(addr));
}

// ---------------------------------------------------------------------------
// Prep (103 blocks x 64 thr): every thread does <=7 independent loads -> one
// DRAM round trip. Packs W1/W3 fragments, converts W2/BN2 to half, folds BN.
// ---------------------------------------------------------------------------
__global__ void __launch_bounds__(64) k_prep(
    const float* __restrict__ W1, const float* __restrict__ W2,
    const float* __restrict__ W3,
    const float* __restrict__ g1, const float* __restrict__ b1,
    const float* __restrict__ m1, const float* __restrict__ v1,
    const float* __restrict__ g2, const float* __restrict__ b2,
    const float* __restrict__ m2, const float* __restrict__ v2,
    const float* __restrict__ g3, const float* __restrict__ b3,
    const float* __restrict__ m3, const float* __restrict__ v3)
{
    const int b    = blockIdx.x;
    const int tid  = threadIdx.x;
    const int lane = tid & 31;
    const int g    = lane >> 2;
    const int t    = lane & 3;
    const int i    = tid >> 5;        // 0/1

    if (b < 48) {                     // W1 fragment (w, s) = (b>>1, b&1)
        const int w = b >> 1, s = b & 1;
        const int col = w * 8 + g;
        const int k0 = 16 * s + 2 * t + 8 * i;
        g_W1f[((w * 2 + s) * 2 + i) * 32 + lane] =
            packh(__float2half(W1[(k0)     * HID + col]),
                  __float2half(W1[(k0 + 1) * HID + col]));
    } else if (b < 96) {              // W3 fragment (j, s)
        const int idx = b - 48;
        const int j = idx / 12, s = idx % 12;
        const int col = j * 8 + g;
        const int k0 = 16 * s + 2 * t + 8 * i;
        g_W3f[((j * 12 + s) * 2 + i) * 32 + lane] =
            packh(__float2half(W3[(k0)     * COUT + col]),
                  __float2half(W3[(k0 + 1) * COUT + col]));
    } else if (b == 96) {             // BN1 fold (fp32)
        for (int c = tid; c < HID; c += 64) {
            const float s = g1[c] * rsqrtf(v1[c] + EPSV);
            g_s1[c] = s; g_c1[c] = b1[c] - m1[c] * s;
        }
    } else if (b == 97) {             // BN2 fold (fp16)
        for (int c = tid; c < HID; c += 64) {
            const float s = g2[c] * rsqrtf(v2[c] + EPSV);
            g_s2h[c] = __float2half(s);
            g_c2h[c] = __float2half(b2[c] - m2[c] * s);
        }
    } else if (b < 102) {             // W2 -> half, quarter per block
        const int q = b - 98;
        const int base = q * (KOFF * HID / 4);
        for (int c = tid; c < KOFF * HID / 4; c += 64)
            g_W2h[base + c] = __float2half(W2[base + c]);
    } else {                          // BN3 fold (fp32)
        for (int c = tid; c < COUT; c += 64) {
            const float s = g3[c] * rsqrtf(v3[c] + EPSV);
            g_s3[c] = s; g_c3[c] = b3[c] - m3[c] * s;
        }
    }
}

// ---------------------------------------------------------------------------
// Kernel 1 (MMA): expand 1x1 conv + BN1 + relu6 -> g_x1 (fp16)
// Block = 768 thr = 24 warps; warp w owns output cols [8w, 8w+8).
// 64-row tile; feats staged fp16 in smem (stride 40 halves). A-fragments via
// ldmatrix.x4 (bank-clean: 20r mod 32 distinct over 8 rows).
// ---------------------------------------------------------------------------
#define FST   40
#define XST   208   // epilogue smem stride (halves) = 26 uint4

__global__ void __launch_bounds__(768) k_expand(
    const float* __restrict__ feats, int N)
{
    __shared__ __align__(16) __half sf[64 * FST];
    __shared__ __align__(16) __half sx[64 * XST];

    const int tid  = threadIdx.x;
    const int w    = tid >> 5;
    const int lane = tid & 31;
    const int g    = lane >> 2;
    const int t    = lane & 3;
    const int colb = w * 8;
    const int c0   = colb + 2 * t;

    unsigned bf[2][2];
#pragma unroll
    for (int s = 0; s < 2; s++)
#pragma unroll
        for (int i = 0; i < 2; i++)
            bf[s][i] = g_W1f[((w * 2 + s) * 2 + i) * 32 + lane];

    const float2 sv = *reinterpret_cast<const float2*>(g_s1 + c0);
    const float2 cv = *reinterpret_cast<const float2*>(g_c1 + c0);

    const int r0 = blockIdx.x * 64;

#pragma unroll
    for (int i = tid; i < 64 * CIN; i += 768) {
        const int r = i >> 5, c = i & 31;
        const int row = r0 + r;
        const float v = (row < N) ? feats[row * CIN + c] : 0.0f;
        sf[r * FST + c] = __float2half(v);
    }
    __syncthreads();

    // ldmatrix lane address: rows (lane>>3&1)*8+(lane&7), col (lane>>4)*8
    const int lrow = ((lane >> 3) & 1) * 8 + (lane & 7);
    const int lcol = (lane >> 4) * 8;
    const unsigned sfu =
        (unsigned)__cvta_generic_to_shared(sf) + (lrow * FST + lcol) * 2;

#pragma unroll
    for (int sub = 0; sub < 4; sub++) {
        float d0 = 0.f, d1 = 0.f, d2 = 0.f, d3 = 0.f;
        const unsigned abase = sfu + sub * 16 * FST * 2;
#pragma unroll
        for (int s = 0; s < 2; s++) {
            unsigned a0, a1, a2, a3;
            ldsm_x4(a0, a1, a2, a3, abase + s * 32);
            mma16816(d0, d1, d2, d3, a0, a1, a2, a3, bf[s][0], bf[s][1]);
        }
        const int rlo = sub * 16 + g;
        const int rhi = rlo + 8;
        *reinterpret_cast<unsigned*>(sx + rlo * XST + c0) =
            f2toh2(relu6f(fmaf(d0, sv.x, cv.x)), relu6f(fmaf(d1, sv.y, cv.y)));
        *reinterpret_cast<unsigned*>(sx + rhi * XST + c0) =
            f2toh2(relu6f(fmaf(d2, sv.x, cv.x)), relu6f(fmaf(d3, sv.y, cv.y)));
    }
    __syncthreads();

    // coalesced store: 64 rows x 24 uint4
    uint4* xg = reinterpret_cast<uint4*>(g_x1);
    const uint4* sxb = reinterpret_cast<const uint4*>(sx);
#pragma unroll
    for (int i = tid; i < 64 * 24; i += 768) {
        const int r = i / 24, ch = i % 24;
        const int row = r0 + r;
        if (row < N) xg[(size_t)row * 24 + ch] = sxb[r * 26 + ch];
    }
}

// ---------------------------------------------------------------------------
// Kernel 2 (FUSED): depthwise gather (half2 datapath) + BN2 + relu6 -> smem
// tile -> project MMA (ldmatrix A-fragments) + BN3 + residual -> out (fp32).
// ---------------------------------------------------------------------------
#define ZST 200   // halves; 25 uint4 per row; ldmatrix bank-clean (4r mod 32)

__global__ void __launch_bounds__(512, 2) k_dwproj(
    const int* __restrict__ nbr,
    const float* __restrict__ feats, float* __restrict__ out, int N)
{
    __shared__ __align__(16) __half zs[64 * ZST];       // 25.6 KB
    __shared__ __align__(16) __half W2s[KOFF * HID];    // 3.4 KB
    __shared__ __align__(16) __half s2s[HID];
    __shared__ __align__(16) __half c2s[HID];
    __shared__ __align__(16) int    nbs[64 * KOFF];     // 2.3 KB

    const int tid  = threadIdx.x;
    const int lane = tid & 31;
    const int w    = tid >> 5;
    const int r0   = blockIdx.x * 64;

    // stage half W2 / BN2 (uint4 copies) and the nbr tile
    {
        const uint4* src = reinterpret_cast<const uint4*>(g_W2h);
        uint4* dst = reinterpret_cast<uint4*>(W2s);
        for (int i = tid; i < KOFF * HID / 8; i += 512) dst[i] = src[i];
        if (tid < HID / 8) {
            reinterpret_cast<uint4*>(s2s)[tid] =
                reinterpret_cast<const uint4*>(g_s2h)[tid];
            reinterpret_cast<uint4*>(c2s)[tid] =
                reinterpret_cast<const uint4*>(g_c2h)[tid];
        }
    }
    for (int i = tid; i < 64 * KOFF; i += 512) {
        const int row = r0 + i / KOFF;
        nbs[i] = (row < N) ? nbr[row * KOFF + (i % KOFF)] : -1;
    }
    __syncthreads();

    // ---- gather + depthwise (half2) + BN2 + relu6 -> zs ----
    const uint4* xg = reinterpret_cast<const uint4*>(g_x1);
    uint4* zsb = reinterpret_cast<uint4*>(zs);
    const __half2 zero2 = __floats2half2_rn(0.f, 0.f);
    const __half2 six2  = __floats2half2_rn(6.f, 6.f);

#pragma unroll
    for (int it = 0; it < 3; it++) {
        const int i    = tid + it * 512;
        const int grpI = i >> 3;            // (row, 128B segment)
        const int l    = i & 7;
        const int rloc = grpI / 3;
        const int seg  = grpI % 3;
        const int ch   = seg * 8 + l;       // uint4 chunk 0..23
        const int ch8  = ch * 8;            // first channel (half index)

        int ids[KOFF];
#pragma unroll
        for (int k = 0; k < KOFF; k++) ids[k] = nbs[rloc * KOFF + k];

        uint4 v[KOFF];
#pragma unroll
        for (int k = 0; k < KOFF; k++) {
            v[k] = make_uint4(0u, 0u, 0u, 0u);
            if (ids[k] >= 0) v[k] = xg[(size_t)ids[k] * 24 + ch];
        }

        __half2 a0 = zero2, a1 = zero2, a2 = zero2, a3 = zero2;
#pragma unroll
        for (int k = 0; k < KOFF; k++) {
            const uint4 wv = *reinterpret_cast<const uint4*>(W2s + k * HID + ch8);
            a0 = __hfma2(u2h2(v[k].x), u2h2(wv.x), a0);
            a1 = __hfma2(u2h2(v[k].y), u2h2(wv.y), a1);
            a2 = __hfma2(u2h2(v[k].z), u2h2(wv.z), a2);
            a3 = __hfma2(u2h2(v[k].w), u2h2(wv.w), a3);
        }

        const uint4 sv4 = *reinterpret_cast<const uint4*>(s2s + ch8);
        const uint4 cv4 = *reinterpret_cast<const uint4*>(c2s + ch8);
        uint4 o;
        o.x = h2u(__hmin2(six2, __hmax2(zero2, __hfma2(a0, u2h2(sv4.x), u2h2(cv4.x)))));
        o.y = h2u(__hmin2(six2, __hmax2(zero2, __hfma2(a1, u2h2(sv4.y), u2h2(cv4.y)))));
        o.z = h2u(__hmin2(six2, __hmax2(zero2, __hfma2(a2, u2h2(sv4.z), u2h2(cv4.z)))));
        o.w = h2u(__hmin2(six2, __hmax2(zero2, __hfma2(a3, u2h2(sv4.w), u2h2(cv4.w)))));
        zsb[rloc * 25 + ch] = o;
    }

    // ---- project MMA + BN3 + residual ----
    const int g  = lane >> 2;
    const int t  = lane & 3;
    const int j  = w & 3;                  // n-tile
    const int rs = w >> 2;                 // row subtile
    const int c0 = 8 * j + 2 * t;

    unsigned bf[12][2];
#pragma unroll
    for (int s = 0; s < 12; s++) {
        bf[s][0] = g_W3f[((j * 12 + s) * 2 + 0) * 32 + lane];
        bf[s][1] = g_W3f[((j * 12 + s) * 2 + 1) * 32 + lane];
    }
    const float2 sv = *reinterpret_cast<const float2*>(g_s3 + c0);
    const float2 cv = *reinterpret_cast<const float2*>(g_c3 + c0);
    __syncthreads();

    const int lrow = ((lane >> 3) & 1) * 8 + (lane & 7);
    const int lcol = (lane >> 4) * 8;
    const unsigned zsu = (unsigned)__cvta_generic_to_shared(zs) +
                         ((rs * 16 + lrow) * ZST + lcol) * 2;

    float d0 = 0.f, d1 = 0.f, d2 = 0.f, d3 = 0.f;
#pragma unroll
    for (int s = 0; s < 12; s++) {
        unsigned a0, a1, a2, a3;
        ldsm_x4(a0, a1, a2, a3, zsu + s * 32);
        mma16816(d0, d1, d2, d3, a0, a1, a2, a3, bf[s][0], bf[s][1]);
    }

    const int rlo = r0 + rs * 16 + g;
    const int rhi = rlo + 8;
    if (rlo < N) {
        const float2 fi = *reinterpret_cast<const float2*>(feats + rlo * COUT + c0);
        float2 o;
        o.x = fmaf(d0, sv.x, cv.x) + fi.x;
        o.y = fmaf(d1, sv.y, cv.y) + fi.y;
        *reinterpret_cast<float2*>(out + rlo * COUT + c0) = o;
    }
    if (rhi < N) {
        const float2 fi = *reinterpret_cast<const float2*>(feats + rhi * COUT + c0);
        float2 o;
        o.x = fmaf(d2, sv.x, cv.x) + fi.x;
        o.y = fmaf(d3, sv.y, cv.y) + fi.y;
        *reinterpret_cast<float2*>(out + rhi * COUT + c0) = o;
    }
}

// ---------------------------------------------------------------------------
extern "C" void kernel_launch(void* const* d_in, const int* in_sizes, int n_in,
                              void* d_out, int out_size)
{
    const float* feats = (const float*)d_in[0];
    const int*   nbr   = (const int*)  d_in[1];
    const float* W1    = (const float*)d_in[2];
    const float* W2    = (const float*)d_in[3];
    const float* W3    = (const float*)d_in[4];
    const float* g1 = (const float*)d_in[5],  *b1 = (const float*)d_in[6];
    const float* m1 = (const float*)d_in[7],  *v1 = (const float*)d_in[8];
    const float* g2 = (const float*)d_in[9],  *b2 = (const float*)d_in[10];
    const float* m2 = (const float*)d_in[11], *v2 = (const float*)d_in[12];
    const float* g3 = (const float*)d_in[13], *b3 = (const float*)d_in[14];
    const float* m3 = (const float*)d_in[15], *v3 = (const float*)d_in[16];
    float* out = (float*)d_out;

    int N = in_sizes[0] / CIN;
    if (N > MAXN) N = MAXN;

    const int tiles = (N + 63) / 64;

    // K0: weight packing + BN fold (one DRAM round trip per thread)
    k_prep<<<103, 64>>>(W1, W2, W3, g1, b1, m1, v1,
                        g2, b2, m2, v2, g3, b3, m3, v3);

    // K1: expand (MMA, ldmatrix)
    k_expand<<<tiles, 768>>>(feats, N);

    // K2: fused depthwise gather (half2) + project (MMA, ldmatrix) + residual
    k_dwproj<<<tiles, 512>>>(nbr, feats, out, N);
}

// round 16
// speedup vs baseline: 1.7937x; 1.0654x over previous
#include <cuda_runtime.h>
#include <cuda_fp16.h>

#define MAXN   200000
#define CIN    32
#define HID    192
#define KOFF   9
#define COUT   32
#define EPSV   1e-5f

// fp16 scratch: expanded activations x1 = relu6(bn1(feats@W1)) [N,192].
// 76.8MB -> largely L2-resident (126MB L2); dw+proj fused so no z stream.
__device__ __half g_x1[(size_t)MAXN * HID];

// constants produced by k_expand block 0 for k_dwproj (next launch):
__device__ unsigned g_W3f[4 * 12 * 2 * 32];   // [j][s][i][lane] fragments
__device__ __align__(16) __half g_W2h[KOFF * HID];  // s2-folded W2, fp16
__device__ __align__(16) __half g_c2h[HID];         // folded BN2 offset
__device__ float g_s3[COUT], g_c3[COUT];            // folded BN3

__device__ __forceinline__ float relu6f(float x) {
    return fminf(fmaxf(x, 0.0f), 6.0f);
}
__device__ __forceinline__ unsigned int f2toh2(float a, float b) {
    __half2 h = __floats2half2_rn(a, b);
    return *reinterpret_cast<unsigned int*>(&h);
}
__device__ __forceinline__ unsigned int packh(__half lo, __half hi) {
    __half2 h = __halves2half2(lo, hi);
    return *reinterpret_cast<unsigned int*>(&h);
}
__device__ __forceinline__ __half2 u2h2(unsigned u) {
    return *reinterpret_cast<__half2*>(&u);
}
__device__ __forceinline__ unsigned h2u(__half2 h) {
    return *reinterpret_cast<unsigned*>(&h);
}

// m16n8k16 fp16 x fp16 -> fp32 MMA
__device__ __forceinline__ void mma16816(
    float& d0, float& d1, float& d2, float& d3,
    unsigned a0, unsigned a1, unsigned a2, unsigned a3,
    unsigned b0, unsigned b1)
{
    asm volatile(
        "mma.sync.aligned.m16n8k16.row.col.f32.f16.f16.f32 "
        "{%0,%1,%2,%3}, {%4,%5,%6,%7}, {%8,%9}, {%0,%1,%2,%3};\n"
        : "+f"(d0), "+f"(d1), "+f"(d2), "+f"(d3)
        : "r"(a0), "r"(a1), "r"(a2), "r"(a3), "r"(b0), "r"(b1));
}

// ldmatrix x4: full m16n8k16 A fragment in one instruction.
__device__ __forceinline__ void ldsm_x4(
    unsigned& r0, unsigned& r1, unsigned& r2, unsigned& r3, unsigned addr)
{
    asm volatile(
        "ldmatrix.sync.aligned.m8n8.x4.shared.b16 {%0,%1,%2,%3}, [%4];\n"
        : "=r"(r0), "=r"(r1), "=r"(r2), "=r"(r3) : "r"(addr));
}

// ---------------------------------------------------------------------------
// Kernel 1 (MMA): expand 1x1 conv + BN1 + relu6 -> g_x1 (fp16)
// Block = 768 thr = 24 warps; warp w owns output cols [8w, 8w+8).
// W1 fragments + BN1 fold are built inline (L2-hit after first wave).
// Block 0 additionally packs all k_dwproj constants (W3f, s2-folded W2h,
// c2h, BN3) — hidden behind the other blocks' work.
// ---------------------------------------------------------------------------
#define FST   40    // feats smem row stride (halves)
#define XST   208   // epilogue smem stride (halves) = 26 uint4

__global__ void __launch_bounds__(768) k_expand(
    const float* __restrict__ feats,
    const float* __restrict__ W1, const float* __restrict__ W2,
    const float* __restrict__ W3,
    const float* __restrict__ g1, const float* __restrict__ b1,
    const float* __restrict__ m1, const float* __restrict__ v1,
    const float* __restrict__ g2, const float* __restrict__ b2,
    const float* __restrict__ m2, const float* __restrict__ v2,
    const float* __restrict__ g3, const float* __restrict__ b3,
    const float* __restrict__ m3, const float* __restrict__ v3,
    int N)
{
    __shared__ __align__(16) __half sf[64 * FST];
    __shared__ __align__(16) __half sx[64 * XST];

    const int tid  = threadIdx.x;
    const int w    = tid >> 5;
    const int lane = tid & 31;
    const int g    = lane >> 2;
    const int t    = lane & 3;
    const int colb = w * 8;
    const int c0   = colb + 2 * t;
    const int c1   = c0 + 1;

    // ---- block 0: pack dwproj constants (independent extra duty) ----
    if (blockIdx.x == 0) {
        if (tid < 128) {            // W3 fragments: j = tid>>5
            const int j = tid >> 5;
            const int col = j * 8 + g;
#pragma unroll
            for (int s = 0; s < 12; s++)
#pragma unroll
                for (int i = 0; i < 2; i++) {
                    const int k0 = 16 * s + 2 * t + 8 * i;
                    g_W3f[((j * 12 + s) * 2 + i) * 32 + lane] =
                        packh(__float2half(W3[(k0)     * COUT + col]),
                              __float2half(W3[(k0 + 1) * COUT + col]));
                }
        }
        // s2-folded W2 -> half
        for (int i = tid; i < KOFF * HID; i += 768) {
            const int ch = i % HID;
            const float s2 = g2[ch] * rsqrtf(v2[ch] + EPSV);
            g_W2h[i] = __float2half(W2[i] * s2);
        }
        if (tid < HID) {            // folded BN2 offset
            const float s2 = g2[tid] * rsqrtf(v2[tid] + EPSV);
            g_c2h[tid] = __float2half(b2[tid] - m2[tid] * s2);
        }
        if (tid < COUT) {           // BN3 fold
            const float s3 = g3[tid] * rsqrtf(v3[tid] + EPSV);
            g_s3[tid] = s3; g_c3[tid] = b3[tid] - m3[tid] * s3;
        }
    }

    // ---- inline W1 fragments + BN1 fold ----
    unsigned bf[2][2];
#pragma unroll
    for (int s = 0; s < 2; s++) {
        const int col = colb + g;
        const int k0 = 16 * s + 2 * t;
        bf[s][0] = packh(__float2half(W1[(k0)     * HID + col]),
                         __float2half(W1[(k0 + 1) * HID + col]));
        bf[s][1] = packh(__float2half(W1[(k0 + 8) * HID + col]),
                         __float2half(W1[(k0 + 9) * HID + col]));
    }
    const float s_a = g1[c0] * rsqrtf(v1[c0] + EPSV);
    const float o_a = b1[c0] - m1[c0] * s_a;
    const float s_b = g1[c1] * rsqrtf(v1[c1] + EPSV);
    const float o_b = b1[c1] - m1[c1] * s_b;

    const int r0 = blockIdx.x * 64;

    // ---- vectorized staging: 512 float4 loads, STS.64 stores ----
    if (tid < 512) {
        const int r  = tid >> 3;          // 0..63
        const int c4 = tid & 7;           // float4 index in row
        const int row = r0 + r;
        float4 f = make_float4(0.f, 0.f, 0.f, 0.f);
        if (row < N)
            f = *reinterpret_cast<const float4*>(feats + row * CIN + c4 * 4);
        uint2 h;
        h.x = f2toh2(f.x, f.y);
        h.y = f2toh2(f.z, f.w);
        *reinterpret_cast<uint2*>(sf + r * FST + c4 * 4) = h;
    }
    __syncthreads();

    // ldmatrix lane address: rows (lane>>3&1)*8+(lane&7), col (lane>>4)*8
    const int lrow = ((lane >> 3) & 1) * 8 + (lane & 7);
    const int lcol = (lane >> 4) * 8;
    const unsigned sfu =
        (unsigned)__cvta_generic_to_shared(sf) + (lrow * FST + lcol) * 2;

#pragma unroll
    for (int sub = 0; sub < 4; sub++) {
        float d0 = 0.f, d1 = 0.f, d2 = 0.f, d3 = 0.f;
        const unsigned abase = sfu + sub * 16 * FST * 2;
#pragma unroll
        for (int s = 0; s < 2; s++) {
            unsigned a0, a1, a2, a3;
            ldsm_x4(a0, a1, a2, a3, abase + s * 32);
            mma16816(d0, d1, d2, d3, a0, a1, a2, a3, bf[s][0], bf[s][1]);
        }
        const int rlo = sub * 16 + g;
        const int rhi = rlo + 8;
        *reinterpret_cast<unsigned*>(sx + rlo * XST + c0) =
            f2toh2(relu6f(fmaf(d0, s_a, o_a)), relu6f(fmaf(d1, s_b, o_b)));
        *reinterpret_cast<unsigned*>(sx + rhi * XST + c0) =
            f2toh2(relu6f(fmaf(d2, s_a, o_a)), relu6f(fmaf(d3, s_b, o_b)));
    }
    __syncthreads();

    // coalesced store: 64 rows x 24 uint4
    uint4* xg = reinterpret_cast<uint4*>(g_x1);
    const uint4* sxb = reinterpret_cast<const uint4*>(sx);
#pragma unroll
    for (int i = tid; i < 64 * 24; i += 768) {
        const int r = i / 24, ch = i % 24;
        const int row = r0 + r;
        if (row < N) xg[(size_t)row * 24 + ch] = sxb[r * 26 + ch];
    }
}

// ---------------------------------------------------------------------------
// Kernel 2 (FUSED): depthwise gather (half2 datapath, BN2 pre-folded into
// W2h/c2h) + relu6 -> smem tile -> project MMA + BN3 + residual -> out.
// ---------------------------------------------------------------------------
#define ZST 200   // halves; 25 uint4 per row; ldmatrix bank-clean (4r mod 32)

__global__ void __launch_bounds__(512, 2) k_dwproj(
    const int* __restrict__ nbr,
    const float* __restrict__ feats, float* __restrict__ out, int N)
{
    __shared__ __align__(16) __half zs[64 * ZST];       // 25.6 KB
    __shared__ __align__(16) __half W2s[KOFF * HID];    // 3.4 KB (s2-folded)
    __shared__ __align__(16) __half c2s[HID];
    __shared__ __align__(16) int    nbs[64 * KOFF];     // 2.3 KB

    const int tid  = threadIdx.x;
    const int lane = tid & 31;
    const int w    = tid >> 5;
    const int r0   = blockIdx.x * 64;

    // stage folded W2 / c2 (uint4 copies) and the nbr tile
    {
        const uint4* src = reinterpret_cast<const uint4*>(g_W2h);
        uint4* dst = reinterpret_cast<uint4*>(W2s);
        for (int i = tid; i < KOFF * HID / 8; i += 512) dst[i] = src[i];
        if (tid < HID / 8)
            reinterpret_cast<uint4*>(c2s)[tid] =
                reinterpret_cast<const uint4*>(g_c2h)[tid];
    }
    for (int i = tid; i < 64 * KOFF; i += 512) {
        const int row = r0 + i / KOFF;
        nbs[i] = (row < N) ? nbr[row * KOFF + (i % KOFF)] : -1;
    }
    __syncthreads();

    // ---- gather + depthwise (half2) + relu6 -> zs ----
    const uint4* xg = reinterpret_cast<const uint4*>(g_x1);
    uint4* zsb = reinterpret_cast<uint4*>(zs);
    const __half2 zero2 = __floats2half2_rn(0.f, 0.f);
    const __half2 six2  = __floats2half2_rn(6.f, 6.f);

#pragma unroll
    for (int it = 0; it < 3; it++) {
        const int i    = tid + it * 512;
        const int grpI = i >> 3;            // (row, 128B segment)
        const int l    = i & 7;
        const int rloc = grpI / 3;
        const int seg  = grpI % 3;
        const int ch   = seg * 8 + l;       // uint4 chunk 0..23
        const int ch8  = ch * 8;            // first channel (half index)

        int ids[KOFF];
#pragma unroll
        for (int k = 0; k < KOFF; k++) ids[k] = nbs[rloc * KOFF + k];

        uint4 v[KOFF];
#pragma unroll
        for (int k = 0; k < KOFF; k++) {
            v[k] = make_uint4(0u, 0u, 0u, 0u);
            if (ids[k] >= 0) v[k] = xg[(size_t)ids[k] * 24 + ch];
        }

        // accumulators start at the folded BN2 offset
        const uint4 cv4 = *reinterpret_cast<const uint4*>(c2s + ch8);
        __half2 a0 = u2h2(cv4.x), a1 = u2h2(cv4.y);
        __half2 a2 = u2h2(cv4.z), a3 = u2h2(cv4.w);
#pragma unroll
        for (int k = 0; k < KOFF; k++) {
            const uint4 wv = *reinterpret_cast<const uint4*>(W2s + k * HID + ch8);
            a0 = __hfma2(u2h2(v[k].x), u2h2(wv.x), a0);
            a1 = __hfma2(u2h2(v[k].y), u2h2(wv.y), a1);
            a2 = __hfma2(u2h2(v[k].z), u2h2(wv.z), a2);
            a3 = __hfma2(u2h2(v[k].w), u2h2(wv.w), a3);
        }

        uint4 o;
        o.x = h2u(__hmin2(six2, __hmax2(zero2, a0)));
        o.y = h2u(__hmin2(six2, __hmax2(zero2, a1)));
        o.z = h2u(__hmin2(six2, __hmax2(zero2, a2)));
        o.w = h2u(__hmin2(six2, __hmax2(zero2, a3)));
        zsb[rloc * 25 + ch] = o;
    }

    // ---- project MMA + BN3 + residual ----
    const int g  = lane >> 2;
    const int t  = lane & 3;
    const int j  = w & 3;                  // n-tile
    const int rs = w >> 2;                 // row subtile
    const int c0 = 8 * j + 2 * t;

    unsigned bf[12][2];
#pragma unroll
    for (int s = 0; s < 12; s++) {
        bf[s][0] = g_W3f[((j * 12 + s) * 2 + 0) * 32 + lane];
        bf[s][1] = g_W3f[((j * 12 + s) * 2 + 1) * 32 + lane];
    }
    const float2 sv = *reinterpret_cast<const float2*>(g_s3 + c0);
    const float2 cv = *reinterpret_cast<const float2*>(g_c3 + c0);
    __syncthreads();

    const int lrow = ((lane >> 3) & 1) * 8 + (lane & 7);
    const int lcol = (lane >> 4) * 8;
    const unsigned zsu = (unsigned)__cvta_generic_to_shared(zs) +
                         ((rs * 16 + lrow) * ZST + lcol) * 2;

    float d0 = 0.f, d1 = 0.f, d2 = 0.f, d3 = 0.f;
#pragma unroll
    for (int s = 0; s < 12; s++) {
        unsigned a0, a1, a2, a3;
        ldsm_x4(a0, a1, a2, a3, zsu + s * 32);
        mma16816(d0, d1, d2, d3, a0, a1, a2, a3, bf[s][0], bf[s][1]);
    }

    const int rlo = r0 + rs * 16 + g;
    const int rhi = rlo + 8;
    if (rlo < N) {
        const float2 fi = *reinterpret_cast<const float2*>(feats + rlo * COUT + c0);
        float2 o;
        o.x = fmaf(d0, sv.x, cv.x) + fi.x;
        o.y = fmaf(d1, sv.y, cv.y) + fi.y;
        *reinterpret_cast<float2*>(out + rlo * COUT + c0) = o;
    }
    if (rhi < N) {
        const float2 fi = *reinterpret_cast<const float2*>(feats + rhi * COUT + c0);
        float2 o;
        o.x = fmaf(d2, sv.x, cv.x) + fi.x;
        o.y = fmaf(d3, sv.y, cv.y) + fi.y;
        *reinterpret_cast<float2*>(out + rhi * COUT + c0) = o;
    }
}

// ---------------------------------------------------------------------------
extern "C" void kernel_launch(void* const* d_in, const int* in_sizes, int n_in,
                              void* d_out, int out_size)
{
    const float* feats = (const float*)d_in[0];
    const int*   nbr   = (const int*)  d_in[1];
    const float* W1    = (const float*)d_in[2];
    const float* W2    = (const float*)d_in[3];
    const float* W3    = (const float*)d_in[4];
    const float* g1 = (const float*)d_in[5],  *b1 = (const float*)d_in[6];
    const float* m1 = (const float*)d_in[7],  *v1 = (const float*)d_in[8];
    const float* g2 = (const float*)d_in[9],  *b2 = (const float*)d_in[10];
    const float* m2 = (const float*)d_in[11], *v2 = (const float*)d_in[12];
    const float* g3 = (const float*)d_in[13], *b3 = (const float*)d_in[14];
    const float* m3 = (const float*)d_in[15], *v3 = (const float*)d_in[16];
    float* out = (float*)d_out;

    int N = in_sizes[0] / CIN;
    if (N > MAXN) N = MAXN;

    const int tiles = (N + 63) / 64;

    // K1: expand (MMA) — block 0 also packs dwproj constants
    k_expand<<<tiles, 768>>>(feats, W1, W2, W3,
                             g1, b1, m1, v1, g2, b2, m2, v2,
                             g3, b3, m3, v3, N);

    // K2: fused depthwise gather (half2) + project (MMA) + residual
    k_dwproj<<<tiles, 512>>>(nbr, feats, out, N);
}